// round 1
// baseline (speedup 1.0000x reference)
#include <cuda_runtime.h>
#include <math.h>

// Problem constants (B=2, T=1024)
#define TTOT   2048          // tokens
#define EMBED  1024
#define HID    2048
#define NE     8

#define TM 64
#define TN 64
#define TK 16

// ---------------- scratch (__device__ globals: sanctioned, no allocs) -------
__device__ int   g_counts[NE];
__device__ int   g_slots[NE * TTOT];            // packed = token*2 + kpos
__device__ float g_weights[TTOT * 2];           // sigmoid(top2 logits)
__device__ float g_act[(size_t)NE * TTOT * HID];   // gelu(gate)*up, per expert slot
__device__ float g_tmp[(size_t)TTOT * 2 * EMBED];  // per-(token,kpos) down output

// ---------------------------------------------------------------------------
__global__ void zero_counts_kernel() {
    if (threadIdx.x < NE) g_counts[threadIdx.x] = 0;
}

// One block per token: 8 warps, warp w computes logit for expert w.
__global__ __launch_bounds__(256) void route_kernel(
    const float* __restrict__ gate_in, const float* __restrict__ gate_k)
{
    int t = blockIdx.x;
    int warp = threadIdx.x >> 5, lane = threadIdx.x & 31;
    __shared__ float logits[NE];

    const float* gr = gate_in + (size_t)t * EMBED;
    float sum = 0.f;
    for (int j = lane; j < EMBED; j += 32)
        sum += gr[j] * gate_k[j * NE + warp];
    #pragma unroll
    for (int o = 16; o > 0; o >>= 1)
        sum += __shfl_down_sync(0xFFFFFFFFu, sum, o);
    if (lane == 0) logits[warp] = sum;
    __syncthreads();

    if (threadIdx.x == 0) {
        // top-1: strict > keeps lowest index on ties (matches jax.lax.top_k)
        int b0 = 0; float v0 = logits[0];
        #pragma unroll
        for (int e = 1; e < NE; e++)
            if (logits[e] > v0) { v0 = logits[e]; b0 = e; }
        int b1 = -1; float v1 = -3.0e38f;
        #pragma unroll
        for (int e = 0; e < NE; e++) {
            if (e == b0) continue;
            if (logits[e] > v1) { v1 = logits[e]; b1 = e; }
        }
        g_weights[t * 2 + 0] = 1.f / (1.f + expf(-v0));
        g_weights[t * 2 + 1] = 1.f / (1.f + expf(-v1));
        int s0 = atomicAdd(&g_counts[b0], 1);
        g_slots[b0 * TTOT + s0] = t * 2 + 0;
        int s1 = atomicAdd(&g_counts[b1], 1);
        g_slots[b1 * TTOT + s1] = t * 2 + 1;
    }
}

__device__ __forceinline__ float gelu_tanh(float x) {
    const float c = 0.7978845608028654f;   // sqrt(2/pi)
    float inner = c * (x + 0.044715f * x * x * x);
    return 0.5f * x * (1.f + tanhf(inner));
}

// ---------------- pass 1: act = gelu(x@Wg) * (x@Wu), grouped by expert ------
__global__ __launch_bounds__(256) void expert_gateup_kernel(
    const float* __restrict__ x,
    const float* __restrict__ wg_all,
    const float* __restrict__ wu_all)
{
    int e = blockIdx.z;
    int count = g_counts[e];
    int rowBase = blockIdx.y * TM;
    if (rowBase >= count) return;
    int n0 = blockIdx.x * TN;

    __shared__ float As[TM * TK];
    __shared__ float Bg[TK * TN];
    __shared__ float Bu[TK * TN];
    __shared__ int   rows[TM];

    int tid = threadIdx.x;
    if (tid < TM) {
        int s = rowBase + tid;
        int packed = (s < count) ? g_slots[e * TTOT + s] : 0;
        rows[tid] = packed >> 1;
    }
    __syncthreads();

    const float* wg = wg_all + (size_t)e * EMBED * HID;
    const float* wu = wu_all + (size_t)e * EMBED * HID;

    int ty = tid >> 4, tx = tid & 15;
    int am = tid >> 2;           // 0..63 (A row)
    int ak = (tid & 3) * 4;      // 0,4,8,12 (A k)
    int br = tid >> 4;           // 0..15  (B k-row)
    int bc = (tid & 15) * 4;     // 0..60  (B col)

    const float* xrow = x + (size_t)rows[am] * EMBED;

    float accg[4][4] = {}, accu[4][4] = {};

    for (int k0 = 0; k0 < EMBED; k0 += TK) {
        *(float4*)&As[am * TK + ak] = *(const float4*)(xrow + k0 + ak);
        *(float4*)&Bg[br * TN + bc] =
            *(const float4*)(wg + (size_t)(k0 + br) * HID + n0 + bc);
        *(float4*)&Bu[br * TN + bc] =
            *(const float4*)(wu + (size_t)(k0 + br) * HID + n0 + bc);
        __syncthreads();

        #pragma unroll
        for (int kk = 0; kk < TK; kk++) {
            float a[4];
            #pragma unroll
            for (int i = 0; i < 4; i++) a[i] = As[(ty * 4 + i) * TK + kk];
            float4 bg4 = *(float4*)&Bg[kk * TN + tx * 4];
            float4 bu4 = *(float4*)&Bu[kk * TN + tx * 4];
            float bgv[4] = {bg4.x, bg4.y, bg4.z, bg4.w};
            float buv[4] = {bu4.x, bu4.y, bu4.z, bu4.w};
            #pragma unroll
            for (int i = 0; i < 4; i++)
                #pragma unroll
                for (int j = 0; j < 4; j++) {
                    accg[i][j] += a[i] * bgv[j];
                    accu[i][j] += a[i] * buv[j];
                }
        }
        __syncthreads();
    }

    #pragma unroll
    for (int i = 0; i < 4; i++) {
        int s = rowBase + ty * 4 + i;
        if (s < count) {
            float* dst = g_act + ((size_t)e * TTOT + s) * HID + n0 + tx * 4;
            float4 v;
            v.x = gelu_tanh(accg[i][0]) * accu[i][0];
            v.y = gelu_tanh(accg[i][1]) * accu[i][1];
            v.z = gelu_tanh(accg[i][2]) * accu[i][2];
            v.w = gelu_tanh(accg[i][3]) * accu[i][3];
            *(float4*)dst = v;
        }
    }
}

// ---------------- pass 2: tmp[packed] = scale[e] * (act @ Wd[e]) ------------
__global__ __launch_bounds__(256) void expert_down_kernel(
    const float* __restrict__ wd_all,
    const float* __restrict__ scale)
{
    int e = blockIdx.z;
    int count = g_counts[e];
    int rowBase = blockIdx.y * TM;
    if (rowBase >= count) return;
    int n0 = blockIdx.x * TN;

    __shared__ float As[TM * TK];
    __shared__ float Bs[TK * TN];
    __shared__ int   packedRows[TM];

    int tid = threadIdx.x;
    if (tid < TM) {
        int s = rowBase + tid;
        packedRows[tid] = (s < count) ? g_slots[e * TTOT + s] : 0;
    }
    __syncthreads();

    const float* wd = wd_all + (size_t)e * HID * EMBED;
    const float* arow = g_act + ((size_t)e * TTOT + rowBase) * HID;

    int ty = tid >> 4, tx = tid & 15;
    int am = tid >> 2;
    int ak = (tid & 3) * 4;
    int br = tid >> 4;
    int bc = (tid & 15) * 4;

    float acc[4][4] = {};

    for (int k0 = 0; k0 < HID; k0 += TK) {
        *(float4*)&As[am * TK + ak] =
            *(const float4*)(arow + (size_t)am * HID + k0 + ak);
        *(float4*)&Bs[br * TN + bc] =
            *(const float4*)(wd + (size_t)(k0 + br) * EMBED + n0 + bc);
        __syncthreads();

        #pragma unroll
        for (int kk = 0; kk < TK; kk++) {
            float a[4];
            #pragma unroll
            for (int i = 0; i < 4; i++) a[i] = As[(ty * 4 + i) * TK + kk];
            float4 b4 = *(float4*)&Bs[kk * TN + tx * 4];
            float bv[4] = {b4.x, b4.y, b4.z, b4.w};
            #pragma unroll
            for (int i = 0; i < 4; i++)
                #pragma unroll
                for (int j = 0; j < 4; j++)
                    acc[i][j] += a[i] * bv[j];
        }
        __syncthreads();
    }

    float sc = scale[e];
    #pragma unroll
    for (int i = 0; i < 4; i++) {
        int s = rowBase + ty * 4 + i;
        if (s < count) {
            int packed = packedRows[ty * 4 + i];
            float* dst = g_tmp + (size_t)packed * EMBED + n0 + tx * 4;
            float4 v;
            v.x = acc[i][0] * sc;
            v.y = acc[i][1] * sc;
            v.z = acc[i][2] * sc;
            v.w = acc[i][3] * sc;
            *(float4*)dst = v;
        }
    }
}

// ---------------- combine: out[t] = w0*tmp[t,0] + w1*tmp[t,1] ---------------
__global__ __launch_bounds__(256) void combine_kernel(float* __restrict__ out)
{
    int i = blockIdx.x * blockDim.x + threadIdx.x;   // over TTOT*EMBED
    int t = i >> 10;         // EMBED == 1024
    int n = i & 1023;
    float w0 = g_weights[t * 2 + 0];
    float w1 = g_weights[t * 2 + 1];
    out[i] = w0 * g_tmp[(size_t)(t * 2 + 0) * EMBED + n]
           + w1 * g_tmp[(size_t)(t * 2 + 1) * EMBED + n];
}

// ---------------------------------------------------------------------------
extern "C" void kernel_launch(void* const* d_in, const int* in_sizes, int n_in,
                              void* d_out, int out_size)
{
    const float* x     = (const float*)d_in[0];  // [2048,1024]
    const float* gi    = (const float*)d_in[1];  // [2048,1024]
    const float* gk    = (const float*)d_in[2];  // [1024,8]
    const float* scale = (const float*)d_in[3];  // [8]
    const float* wg    = (const float*)d_in[4];  // [8,1024,2048]
    const float* wu    = (const float*)d_in[5];  // [8,1024,2048]
    const float* wd    = (const float*)d_in[6];  // [8,2048,1024]
    float* out = (float*)d_out;

    zero_counts_kernel<<<1, 32>>>();
    route_kernel<<<TTOT, 256>>>(gi, gk);
    expert_gateup_kernel<<<dim3(HID / TN, TTOT / TM, NE), 256>>>(x, wg, wu);
    expert_down_kernel<<<dim3(EMBED / TN, TTOT / TM, NE), 256>>>(wd, scale);
    combine_kernel<<<(TTOT * EMBED) / 256, 256>>>(out);
}